// round 2
// baseline (speedup 1.0000x reference)
#include <cuda_runtime.h>
#include <cstdint>

// Problem constants (fixed-shape problem)
#define BB 4
#define TT 12
#define NN 10000
#define FF 32
#define EE 160000
#define MM (BB*NN)          // 40000 node-batch rows
#define SLICES (BB*TT)      // 48
#define SL (NN*FF)          // elements per (b,t) slice = 320000

// -------- device scratch (static, no allocation) --------
__device__ float d_XA[SLICES * NN * FF];   // aggregated features, all slices (61.4MB)
__device__ float d_H[MM * FF];             // GRU hidden state
__device__ float d_Hacc[MM * FF];          // attention-weighted accumulator
__device__ float d_deg[NN];
__device__ float d_dinv[NN];
__device__ int   d_cnt[NN];
__device__ int   d_fill[NN];
__device__ int   d_rowptr[NN + 1];
__device__ int   d_csr_row[EE];
__device__ float d_csr_w[EE];
__device__ float d_Wf[3 * 1024];           // folded W'_z, W'_r, W'_h (32x32 each)
__device__ float d_bf[3 * 32];             // folded biases
__device__ float d_probs[TT];              // softmax(attention)

// -------- prep: fold weights, softmax attention --------
__global__ void k_prep(const float* att,
                       const float* Wz, const float* bz, const float* lzw, const float* lzb,
                       const float* Wr, const float* br, const float* lrw, const float* lrb,
                       const float* Wh, const float* bh, const float* lhw, const float* lhb) {
    int tid = threadIdx.x;                 // 1024 threads
    const float* Ws[3]  = {Wz, Wr, Wh};
    const float* bs[3]  = {bz, br, bh};
    const float* ls[3]  = {lzw, lrw, lhw};
    const float* lbs[3] = {lzb, lrb, lhb};
    int k = tid >> 5, j = tid & 31;        // k,j in [0,32)
    #pragma unroll
    for (int g = 0; g < 3; g++) {
        float s = 0.f;
        #pragma unroll
        for (int m = 0; m < 32; m++) s += Ws[g][k * 32 + m] * ls[g][m * 32 + j];
        d_Wf[g * 1024 + k * 32 + j] = s;
    }
    if (tid < 96) {
        int g = tid >> 5; int jj = tid & 31;
        float s = lbs[g][jj];
        for (int m = 0; m < 32; m++) s += bs[g][m] * ls[g][m * 32 + jj];
        d_bf[g * 32 + jj] = s;
    }
    if (tid == 0) {
        float mx = -1e30f;
        for (int i = 0; i < TT; i++) mx = fmaxf(mx, att[i]);
        float e[TT]; float sum = 0.f;
        for (int i = 0; i < TT; i++) { e[i] = expf(att[i] - mx); sum += e[i]; }
        for (int i = 0; i < TT; i++) d_probs[i] = e[i] / sum;
    }
}

// -------- CSR build --------
__global__ void k_zero() {
    int i = blockIdx.x * blockDim.x + threadIdx.x;
    if (i < NN) { d_deg[i] = 0.f; d_cnt[i] = 0; d_fill[i] = 0; }
}

__global__ void k_degcnt(const int* ei, const float* ew) {
    int e = blockIdx.x * blockDim.x + threadIdx.x;
    if (e >= EE) return;
    int col = ei[EE + e];
    atomicAdd(&d_deg[col], ew[e]);
    atomicAdd(&d_cnt[col], 1);
}

__global__ void k_dinv() {
    int n = blockIdx.x * blockDim.x + threadIdx.x;
    if (n >= NN) return;
    float d = d_deg[n] + 1.0f;             // + self loop weight 1.0
    d_dinv[n] = (d > 0.f) ? rsqrtf(fmaxf(d, 1e-12f)) : 0.f;
}

// single-block exclusive scan over d_cnt -> d_rowptr (10000 elements, 10 chunks)
__global__ void k_scan() {
    __shared__ int sh[1024];
    __shared__ int carry;
    if (threadIdx.x == 0) carry = 0;
    __syncthreads();
    for (int base = 0; base < NN; base += 1024) {
        int i = base + threadIdx.x;
        int v = (i < NN) ? d_cnt[i] : 0;
        sh[threadIdx.x] = v;
        __syncthreads();
        for (int off = 1; off < 1024; off <<= 1) {
            int t = (threadIdx.x >= off) ? sh[threadIdx.x - off] : 0;
            __syncthreads();
            sh[threadIdx.x] += t;
            __syncthreads();
        }
        if (i < NN) d_rowptr[i] = carry + sh[threadIdx.x] - v;  // exclusive
        __syncthreads();
        if (threadIdx.x == 0) carry += sh[1023];
        __syncthreads();
    }
    if (threadIdx.x == 0) d_rowptr[NN] = carry;
}

__global__ void k_fill(const int* ei, const float* ew) {
    int e = blockIdx.x * blockDim.x + threadIdx.x;
    if (e >= EE) return;
    int r = ei[e];
    int c = ei[EE + e];
    int pos = d_rowptr[c] + atomicAdd(&d_fill[c], 1);
    d_csr_row[pos] = r;
    d_csr_w[pos] = d_dinv[r] * ew[e] * d_dinv[c];
}

// -------- aggregation: XA[s,n,:] = sum_e norm_e * x[s,row_e,:] + selfw_n * x[s,n,:]
// one warp per (node, group of 8 slices); lane = feature
__global__ void k_agg(const float* __restrict__ x) {
    int w = (blockIdx.x * blockDim.x + threadIdx.x) >> 5;
    int lane = threadIdx.x & 31;
    if (w >= NN * 6) return;
    int n = w / 6, g = w % 6;
    float dn = d_dinv[n];
    float selfw = dn * dn;
    int nb = n * 32 + lane;
    float acc[8];
    #pragma unroll
    for (int u = 0; u < 8; u++)
        acc[u] = selfw * __ldg(&x[(g * 8 + u) * SL + nb]);
    int e0 = d_rowptr[n], e1 = d_rowptr[n + 1];
    for (int e = e0; e < e1; e++) {
        int r = d_csr_row[e];
        float wgt = d_csr_w[e];
        int rb = r * 32 + lane;
        #pragma unroll
        for (int u = 0; u < 8; u++)
            acc[u] += wgt * __ldg(&x[(g * 8 + u) * SL + rb]);
    }
    #pragma unroll
    for (int u = 0; u < 8; u++)
        d_XA[(g * 8 + u) * SL + nb] = acc[u];
}

// -------- fused GRU step (one launch per t), one warp per 4 (b,n) rows --------
__global__ void k_step(int t,
                       const float* __restrict__ lzw,
                       const float* __restrict__ lrw,
                       const float* __restrict__ lhw) {
    __shared__ float sWz[1024], sWr[1024], sWh[1024];
    __shared__ float sUz[1024], sUr[1024], sUh[1024];
    __shared__ float sb[96];
    __shared__ float sprob;
    for (int i = threadIdx.x; i < 1024; i += blockDim.x) {
        sWz[i] = d_Wf[i];
        sWr[i] = d_Wf[1024 + i];
        sWh[i] = d_Wf[2048 + i];
        sUz[i] = lzw[1024 + i];   // bottom half of [64,32] weight
        sUr[i] = lrw[1024 + i];
        sUh[i] = lhw[1024 + i];
    }
    if (threadIdx.x < 96) sb[threadIdx.x] = d_bf[threadIdx.x];
    if (threadIdx.x == 0) sprob = d_probs[t];
    __syncthreads();

    int w = (blockIdx.x * blockDim.x + threadIdx.x) >> 5;
    int lane = threadIdx.x & 31;
    if (w >= MM / 4) return;
    int m0 = w * 4;

    float bz = sb[lane], br = sb[32 + lane], bh = sb[64 + lane];
    float xa[4], h[4], az[4], ar[4], ah[4];
    #pragma unroll
    for (int u = 0; u < 4; u++) {
        int m = m0 + u;
        int b = m / NN;
        int n = m - b * NN;
        xa[u] = d_XA[((b * TT + t) * NN + n) * 32 + lane];
        h[u] = (t == 0) ? 0.f : d_H[m * 32 + lane];
        az[u] = bz; ar[u] = br; ah[u] = bh;
    }
    #pragma unroll
    for (int k = 0; k < 32; k++) {
        float wz = sWz[k * 32 + lane], wr = sWr[k * 32 + lane], wh = sWh[k * 32 + lane];
        float uz = sUz[k * 32 + lane], ur = sUr[k * 32 + lane];
        #pragma unroll
        for (int u = 0; u < 4; u++) {
            float xk = __shfl_sync(0xffffffffu, xa[u], k);
            float hk = __shfl_sync(0xffffffffu, h[u], k);
            az[u] += xk * wz + hk * uz;
            ar[u] += xk * wr + hk * ur;
            ah[u] += xk * wh;
        }
    }
    float z[4], hr[4];
    #pragma unroll
    for (int u = 0; u < 4; u++) {
        z[u] = 1.f / (1.f + __expf(-az[u]));
        float R = 1.f / (1.f + __expf(-ar[u]));
        hr[u] = h[u] * R;
    }
    #pragma unroll
    for (int k = 0; k < 32; k++) {
        float uh = sUh[k * 32 + lane];
        #pragma unroll
        for (int u = 0; u < 4; u++)
            ah[u] += __shfl_sync(0xffffffffu, hr[u], k) * uh;
    }
    #pragma unroll
    for (int u = 0; u < 4; u++) {
        float Ht = tanhf(ah[u]);
        float Hn = z[u] * h[u] + (1.f - z[u]) * Ht;
        int m = m0 + u;
        d_H[m * 32 + lane] = Hn;
        if (t == 0) d_Hacc[m * 32 + lane] = sprob * Hn;
        else        d_Hacc[m * 32 + lane] += sprob * Hn;
    }
}

// -------- final: out = relu(Hacc) @ lin_w + lin_b --------
__global__ void k_final(const float* __restrict__ linw,
                        const float* __restrict__ linb,
                        float* __restrict__ out) {
    __shared__ float sW[1024];
    __shared__ float sb2[32];
    for (int i = threadIdx.x; i < 1024; i += blockDim.x) sW[i] = linw[i];
    if (threadIdx.x < 32) sb2[threadIdx.x] = linb[threadIdx.x];
    __syncthreads();

    int w = (blockIdx.x * blockDim.x + threadIdx.x) >> 5;
    int lane = threadIdx.x & 31;
    if (w >= MM / 4) return;
    int m0 = w * 4;
    float v[4], acc[4];
    #pragma unroll
    for (int u = 0; u < 4; u++) {
        v[u] = fmaxf(d_Hacc[(m0 + u) * 32 + lane], 0.f);
        acc[u] = sb2[lane];
    }
    #pragma unroll
    for (int k = 0; k < 32; k++) {
        float lw = sW[k * 32 + lane];
        #pragma unroll
        for (int u = 0; u < 4; u++)
            acc[u] += __shfl_sync(0xffffffffu, v[u], k) * lw;
    }
    #pragma unroll
    for (int u = 0; u < 4; u++)
        out[(m0 + u) * 32 + lane] = acc[u];
}

extern "C" void kernel_launch(void* const* d_in, const int* in_sizes, int n_in,
                              void* d_out, int out_size) {
    const float* x  = (const float*)d_in[0];
    const int*   ei = (const int*)d_in[1];
    const float* ew = (const float*)d_in[2];

    // Detect weight ordering at runtime:
    //  dict order:      W_z,b_z,lz_w,lz_b, W_r,b_r,lr_w,lr_b, W_h,b_h,lh_w,lh_b  -> in_sizes[5]==2048
    //  signature order: W_z,b_z,W_r,b_r,W_h,b_h, lz_w,lz_b,lr_w,lr_b,lh_w,lh_b  -> in_sizes[5]==1024
    int iWz, iBz, iLzw, iLzb, iWr, iBr, iLrw, iLrb, iWh, iBh, iLhw, iLhb;
    if (in_sizes[5] == 2048) {
        iWz = 3; iBz = 4; iLzw = 5;  iLzb = 6;
        iWr = 7; iBr = 8; iLrw = 9;  iLrb = 10;
        iWh = 11; iBh = 12; iLhw = 13; iLhb = 14;
    } else {
        iWz = 3; iBz = 4; iWr = 5; iBr = 6; iWh = 7; iBh = 8;
        iLzw = 9; iLzb = 10; iLrw = 11; iLrb = 12; iLhw = 13; iLhb = 14;
    }
    const float* Wz  = (const float*)d_in[iWz];
    const float* bz  = (const float*)d_in[iBz];
    const float* lzw = (const float*)d_in[iLzw];
    const float* lzb = (const float*)d_in[iLzb];
    const float* Wr  = (const float*)d_in[iWr];
    const float* br  = (const float*)d_in[iBr];
    const float* lrw = (const float*)d_in[iLrw];
    const float* lrb = (const float*)d_in[iLrb];
    const float* Wh  = (const float*)d_in[iWh];
    const float* bh  = (const float*)d_in[iBh];
    const float* lhw = (const float*)d_in[iLhw];
    const float* lhb = (const float*)d_in[iLhb];
    const float* att  = (const float*)d_in[15];
    const float* linw = (const float*)d_in[16];
    const float* linb = (const float*)d_in[17];
    float* out = (float*)d_out;

    // CSR build + prep
    k_zero<<<(NN + 255) / 256, 256>>>();
    k_prep<<<1, 1024>>>(att, Wz, bz, lzw, lzb, Wr, br, lrw, lrb, Wh, bh, lhw, lhb);
    k_degcnt<<<(EE + 255) / 256, 256>>>(ei, ew);
    k_dinv<<<(NN + 255) / 256, 256>>>();
    k_scan<<<1, 1024>>>();
    k_fill<<<(EE + 255) / 256, 256>>>(ei, ew);

    // aggregation for all 48 (b,t) slices: 60000 warps
    {
        int warps = NN * 6;
        int threads = warps * 32;
        k_agg<<<(threads + 255) / 256, 256>>>(x);
    }

    // GRU recurrence, sequential over T
    {
        int warps = MM / 4;                 // 10000
        int blk = 1024;                     // 32 warps/block
        int grid = (warps * 32 + blk - 1) / blk;
        for (int t = 0; t < TT; t++)
            k_step<<<grid, blk>>>(t, lzw, lrw, lhw);
    }

    // final projection
    {
        int warps = MM / 4;
        int blk = 256;
        int grid = (warps * 32 + blk - 1) / blk;
        k_final<<<grid, blk>>>(linw, linb, out);
    }
    (void)n_in; (void)out_size;
}

// round 3
// speedup vs baseline: 1.9232x; 1.9232x over previous
#include <cuda_runtime.h>
#include <cstdint>

// Problem constants (fixed-shape problem)
#define BB 4
#define TT 12
#define NN 10000
#define FF 32
#define EE 160000
#define MM (BB*NN)          // 40000 rows
#define SLICES (BB*TT)      // 48
#define SL (NN*FF)          // 320000 elements per slice

typedef unsigned long long ull;

// -------- device scratch (static, no allocation) --------
__device__ float d_XA[SLICES * NN * FF];   // aggregated features (61.4MB)
__device__ float d_deg[NN];
__device__ float d_dinv[NN];
__device__ int   d_cnt[NN];
__device__ int   d_fill[NN];
__device__ int   d_rowptr[NN + 1];
__device__ int   d_csr_row[EE];
__device__ float d_csr_w[EE];
__device__ float d_Wpack[32 * 32 * 4];     // [k][j][{Wz',Wr',Wh',Uz}]
__device__ float d_Ur[1024];
__device__ float d_Uh[1024];
__device__ float d_bf[96];                 // folded biases z|r|h
__device__ float d_probs[TT];

// ===================== f32x2 helpers =====================
__device__ __forceinline__ void fma2(ull& d, ull a, ull b) {
    asm("fma.rn.f32x2 %0, %1, %2, %0;" : "+l"(d) : "l"(a), "l"(b));
}
__device__ __forceinline__ ull splat2(float w) {
    ull r; asm("mov.b64 %0, {%1, %1};" : "=l"(r) : "f"(w)); return r;
}
__device__ __forceinline__ float2 unpk(ull a) {
    float2 f; asm("mov.b64 {%0, %1}, %2;" : "=f"(f.x), "=f"(f.y) : "l"(a)); return f;
}

// -------- prep: fold weights, build packed layouts, softmax attention --------
__global__ void k_prep(const float* att,
                       const float* Wz, const float* bz, const float* lzw, const float* lzb,
                       const float* Wr, const float* br, const float* lrw, const float* lrb,
                       const float* Wh, const float* bh, const float* lhw, const float* lhb) {
    int tid = threadIdx.x;                 // 1024 threads
    const float* Ws[3]  = {Wz, Wr, Wh};
    const float* bs[3]  = {bz, br, bh};
    const float* ls[3]  = {lzw, lrw, lhw};
    const float* lbs[3] = {lzb, lrb, lhb};
    int k = tid >> 5, j = tid & 31;
    #pragma unroll
    for (int g = 0; g < 3; g++) {
        float s = 0.f;
        #pragma unroll
        for (int m = 0; m < 32; m++) s += Ws[g][k * 32 + m] * ls[g][m * 32 + j];
        d_Wpack[(k * 32 + j) * 4 + g] = s;   // folded W'_g
    }
    d_Wpack[(k * 32 + j) * 4 + 3] = lzw[(32 + k) * 32 + j];  // Uz
    d_Ur[k * 32 + j] = lrw[(32 + k) * 32 + j];
    d_Uh[k * 32 + j] = lhw[(32 + k) * 32 + j];
    if (tid < 96) {
        int g = tid >> 5; int jj = tid & 31;
        float s = lbs[g][jj];
        for (int m = 0; m < 32; m++) s += bs[g][m] * ls[g][m * 32 + jj];
        d_bf[g * 32 + jj] = s;
    }
    if (tid == 0) {
        float mx = -1e30f;
        for (int i = 0; i < TT; i++) mx = fmaxf(mx, att[i]);
        float e[TT]; float sum = 0.f;
        for (int i = 0; i < TT; i++) { e[i] = expf(att[i] - mx); sum += e[i]; }
        for (int i = 0; i < TT; i++) d_probs[i] = e[i] / sum;
    }
}

// -------- CSR build --------
__global__ void k_zero() {
    int i = blockIdx.x * blockDim.x + threadIdx.x;
    if (i < NN) { d_deg[i] = 0.f; d_cnt[i] = 0; d_fill[i] = 0; }
}

__global__ void k_degcnt(const int* ei, const float* ew) {
    int e = blockIdx.x * blockDim.x + threadIdx.x;
    if (e >= EE) return;
    int col = ei[EE + e];
    atomicAdd(&d_deg[col], ew[e]);
    atomicAdd(&d_cnt[col], 1);
}

__global__ void k_dinv() {
    int n = blockIdx.x * blockDim.x + threadIdx.x;
    if (n >= NN) return;
    float d = d_deg[n] + 1.0f;             // + self loop
    d_dinv[n] = (d > 0.f) ? rsqrtf(fmaxf(d, 1e-12f)) : 0.f;
}

__global__ void k_scan() {
    __shared__ int sh[1024];
    __shared__ int carry;
    if (threadIdx.x == 0) carry = 0;
    __syncthreads();
    for (int base = 0; base < NN; base += 1024) {
        int i = base + threadIdx.x;
        int v = (i < NN) ? d_cnt[i] : 0;
        sh[threadIdx.x] = v;
        __syncthreads();
        for (int off = 1; off < 1024; off <<= 1) {
            int t = (threadIdx.x >= off) ? sh[threadIdx.x - off] : 0;
            __syncthreads();
            sh[threadIdx.x] += t;
            __syncthreads();
        }
        if (i < NN) d_rowptr[i] = carry + sh[threadIdx.x] - v;
        __syncthreads();
        if (threadIdx.x == 0) carry += sh[1023];
        __syncthreads();
    }
    if (threadIdx.x == 0) d_rowptr[NN] = carry;
}

__global__ void k_fill(const int* ei, const float* ew) {
    int e = blockIdx.x * blockDim.x + threadIdx.x;
    if (e >= EE) return;
    int r = ei[e];
    int c = ei[EE + e];
    int pos = d_rowptr[c] + atomicAdd(&d_fill[c], 1);
    d_csr_row[pos] = r;
    d_csr_w[pos] = d_dinv[r] * ew[e] * d_dinv[c];
}

// -------- aggregation: one warp per (node, group of 8 slices) --------
__global__ void k_agg(const float* __restrict__ x) {
    int w = (blockIdx.x * blockDim.x + threadIdx.x) >> 5;
    int lane = threadIdx.x & 31;
    if (w >= NN * 6) return;
    int n = w / 6, g = w % 6;
    float dn = d_dinv[n];
    float selfw = dn * dn;
    int nb = n * 32 + lane;
    float acc[8];
    #pragma unroll
    for (int u = 0; u < 8; u++)
        acc[u] = selfw * __ldg(&x[(g * 8 + u) * SL + nb]);
    int e0 = d_rowptr[n], e1 = d_rowptr[n + 1];
    for (int e = e0; e < e1; e++) {
        int r = d_csr_row[e];
        float wgt = d_csr_w[e];
        int rb = r * 32 + lane;
        #pragma unroll
        for (int u = 0; u < 8; u++)
            acc[u] += wgt * __ldg(&x[(g * 8 + u) * SL + rb]);
    }
    #pragma unroll
    for (int u = 0; u < 8; u++)
        __stcs(&d_XA[(g * 8 + u) * SL + nb], acc[u]);   // streaming: keep x in L2
}

// -------- fused GRU over all T + final projection, one launch --------
// 128 threads (4 warps), warp owns 8 rows; H/Hacc live in registers all 12 steps.
__global__ void __launch_bounds__(128, 4)
k_gru(const float* __restrict__ linw, const float* __restrict__ linb,
      float* __restrict__ out) {
    __shared__ float sW4[4096];            // [k*32+j][4] = {Wz',Wr',Wh',Uz}
    __shared__ float sUr[1024], sUh[1024], sLin[1024];
    __shared__ float sb[96];
    __shared__ float sprob[16];
    __shared__ __align__(16) float stg[4][3][256];   // per-warp xaT | hT | hrT

    int tid = threadIdx.x;
    for (int i = tid; i < 4096; i += 128) sW4[i] = d_Wpack[i];
    for (int i = tid; i < 1024; i += 128) {
        sUr[i] = d_Ur[i]; sUh[i] = d_Uh[i]; sLin[i] = linw[i];
    }
    if (tid < 96) sb[tid] = d_bf[tid];
    if (tid < TT) sprob[tid] = d_probs[tid];
    __syncthreads();

    int w = tid >> 5, j = tid & 31;
    int m0 = blockIdx.x * 32 + w * 8;
    float* xaT = stg[w][0];
    float* hT  = stg[w][1];
    float* hrT = stg[w][2];

    // per-row XA offsets (int fits: < 2^31)
    int off[8];
    #pragma unroll
    for (int r = 0; r < 8; r++) {
        int m = m0 + r;
        int b = m / NN;
        int n = m - b * NN;
        off[r] = b * (TT * SL) + n * 32 + j;
    }

    float h[8], hacc[8], xan[8];
    #pragma unroll
    for (int r = 0; r < 8; r++) {
        h[r] = 0.f; hacc[r] = 0.f;
        xan[r] = __ldg(&d_XA[off[r]]);     // prefetch t=0
    }

    ull bz2 = splat2(sb[j]), br2 = splat2(sb[32 + j]), bh2 = splat2(sb[64 + j]);

    for (int t = 0; t < TT; t++) {
        float xa[8];
        #pragma unroll
        for (int r = 0; r < 8; r++) xa[r] = xan[r];
        if (t + 1 < TT) {
            #pragma unroll
            for (int r = 0; r < 8; r++)
                xan[r] = __ldg(&d_XA[off[r] + (t + 1) * SL]);   // prefetch next step
        }
        __syncwarp();
        ((float4*)(xaT + j * 8))[0] = make_float4(xa[0], xa[1], xa[2], xa[3]);
        ((float4*)(xaT + j * 8))[1] = make_float4(xa[4], xa[5], xa[6], xa[7]);
        ((float4*)(hT  + j * 8))[0] = make_float4(h[0], h[1], h[2], h[3]);
        ((float4*)(hT  + j * 8))[1] = make_float4(h[4], h[5], h[6], h[7]);
        __syncwarp();

        ull az[4], ar[4], ah[4];
        #pragma unroll
        for (int p = 0; p < 4; p++) { az[p] = bz2; ar[p] = br2; ah[p] = bh2; }

        #pragma unroll 4
        for (int k = 0; k < 32; k++) {
            ulonglong2 x01 = ((const ulonglong2*)(xaT + k * 8))[0];  // rows (0,1),(2,3)
            ulonglong2 x23 = ((const ulonglong2*)(xaT + k * 8))[1];  // rows (4,5),(6,7)
            ulonglong2 h01 = ((const ulonglong2*)(hT  + k * 8))[0];
            ulonglong2 h23 = ((const ulonglong2*)(hT  + k * 8))[1];
            float4 w4 = ((const float4*)sW4)[k * 32 + j];
            float urv = sUr[k * 32 + j];
            ull wz2 = splat2(w4.x), wr2 = splat2(w4.y), wh2 = splat2(w4.z);
            ull uz2 = splat2(w4.w), ur2 = splat2(urv);
            ull xp[4] = {x01.x, x01.y, x23.x, x23.y};
            ull hp[4] = {h01.x, h01.y, h23.x, h23.y};
            #pragma unroll
            for (int p = 0; p < 4; p++) {
                fma2(az[p], xp[p], wz2); fma2(az[p], hp[p], uz2);
                fma2(ar[p], xp[p], wr2); fma2(ar[p], hp[p], ur2);
                fma2(ah[p], xp[p], wh2);
            }
        }

        // activations: z = sigmoid(az); hr = h * sigmoid(ar)
        float z[8], hr[8];
        #pragma unroll
        for (int p = 0; p < 4; p++) {
            float2 a = unpk(az[p]);
            float2 b = unpk(ar[p]);
            z[2 * p]     = 1.f / (1.f + __expf(-a.x));
            z[2 * p + 1] = 1.f / (1.f + __expf(-a.y));
            hr[2 * p]     = h[2 * p]     * (1.f / (1.f + __expf(-b.x)));
            hr[2 * p + 1] = h[2 * p + 1] * (1.f / (1.f + __expf(-b.y)));
        }
        __syncwarp();
        ((float4*)(hrT + j * 8))[0] = make_float4(hr[0], hr[1], hr[2], hr[3]);
        ((float4*)(hrT + j * 8))[1] = make_float4(hr[4], hr[5], hr[6], hr[7]);
        __syncwarp();

        #pragma unroll 4
        for (int k = 0; k < 32; k++) {
            ulonglong2 r01 = ((const ulonglong2*)(hrT + k * 8))[0];
            ulonglong2 r23 = ((const ulonglong2*)(hrT + k * 8))[1];
            ull uh2 = splat2(sUh[k * 32 + j]);
            fma2(ah[0], r01.x, uh2); fma2(ah[1], r01.y, uh2);
            fma2(ah[2], r23.x, uh2); fma2(ah[3], r23.y, uh2);
        }

        float pt = sprob[t];
        #pragma unroll
        for (int p = 0; p < 4; p++) {
            float2 a = unpk(ah[p]);
            float ht0 = 2.f / (1.f + __expf(-2.f * a.x)) - 1.f;   // tanh
            float ht1 = 2.f / (1.f + __expf(-2.f * a.y)) - 1.f;
            int r0 = 2 * p, r1 = 2 * p + 1;
            h[r0] = z[r0] * h[r0] + (1.f - z[r0]) * ht0;
            h[r1] = z[r1] * h[r1] + (1.f - z[r1]) * ht1;
            hacc[r0] += pt * h[r0];
            hacc[r1] += pt * h[r1];
        }
    }

    // final: out = relu(Hacc) @ lin_w + lin_b
    __syncwarp();
    ((float4*)(xaT + j * 8))[0] = make_float4(fmaxf(hacc[0], 0.f), fmaxf(hacc[1], 0.f),
                                              fmaxf(hacc[2], 0.f), fmaxf(hacc[3], 0.f));
    ((float4*)(xaT + j * 8))[1] = make_float4(fmaxf(hacc[4], 0.f), fmaxf(hacc[5], 0.f),
                                              fmaxf(hacc[6], 0.f), fmaxf(hacc[7], 0.f));
    __syncwarp();

    ull lb2 = splat2(__ldg(&linb[j]));
    ull acc[4] = {lb2, lb2, lb2, lb2};
    #pragma unroll 4
    for (int k = 0; k < 32; k++) {
        ulonglong2 v01 = ((const ulonglong2*)(xaT + k * 8))[0];
        ulonglong2 v23 = ((const ulonglong2*)(xaT + k * 8))[1];
        ull lw2 = splat2(sLin[k * 32 + j]);
        fma2(acc[0], v01.x, lw2); fma2(acc[1], v01.y, lw2);
        fma2(acc[2], v23.x, lw2); fma2(acc[3], v23.y, lw2);
    }
    #pragma unroll
    for (int p = 0; p < 4; p++) {
        float2 a = unpk(acc[p]);
        out[(m0 + 2 * p) * 32 + j] = a.x;
        out[(m0 + 2 * p + 1) * 32 + j] = a.y;
    }
}

extern "C" void kernel_launch(void* const* d_in, const int* in_sizes, int n_in,
                              void* d_out, int out_size) {
    const float* x  = (const float*)d_in[0];
    const int*   ei = (const int*)d_in[1];
    const float* ew = (const float*)d_in[2];

    // Detect weight ordering (dict vs signature) via in_sizes[5]
    int iWz, iBz, iLzw, iLzb, iWr, iBr, iLrw, iLrb, iWh, iBh, iLhw, iLhb;
    if (in_sizes[5] == 2048) {
        iWz = 3; iBz = 4; iLzw = 5;  iLzb = 6;
        iWr = 7; iBr = 8; iLrw = 9;  iLrb = 10;
        iWh = 11; iBh = 12; iLhw = 13; iLhb = 14;
    } else {
        iWz = 3; iBz = 4; iWr = 5; iBr = 6; iWh = 7; iBh = 8;
        iLzw = 9; iLzb = 10; iLrw = 11; iLrb = 12; iLhw = 13; iLhb = 14;
    }
    const float* Wz  = (const float*)d_in[iWz];
    const float* bz  = (const float*)d_in[iBz];
    const float* lzw = (const float*)d_in[iLzw];
    const float* lzb = (const float*)d_in[iLzb];
    const float* Wr  = (const float*)d_in[iWr];
    const float* br  = (const float*)d_in[iBr];
    const float* lrw = (const float*)d_in[iLrw];
    const float* lrb = (const float*)d_in[iLrb];
    const float* Wh  = (const float*)d_in[iWh];
    const float* bh  = (const float*)d_in[iBh];
    const float* lhw = (const float*)d_in[iLhw];
    const float* lhb = (const float*)d_in[iLhb];
    const float* att  = (const float*)d_in[15];
    const float* linw = (const float*)d_in[16];
    const float* linb = (const float*)d_in[17];
    float* out = (float*)d_out;

    k_zero<<<(NN + 255) / 256, 256>>>();
    k_prep<<<1, 1024>>>(att, Wz, bz, lzw, lzb, Wr, br, lrw, lrb, Wh, bh, lhw, lhb);
    k_degcnt<<<(EE + 255) / 256, 256>>>(ei, ew);
    k_dinv<<<(NN + 255) / 256, 256>>>();
    k_scan<<<1, 1024>>>();
    k_fill<<<(EE + 255) / 256, 256>>>(ei, ew);

    {   // aggregation: 60000 warps
        int threads = NN * 6 * 32;
        k_agg<<<(threads + 255) / 256, 256>>>(x);
    }

    // fused GRU (all 12 steps) + final projection: one launch
    k_gru<<<MM / 32, 128>>>(linw, linb, out);

    (void)n_in; (void)out_size;
}